// round 12
// baseline (speedup 1.0000x reference)
#include <cuda_runtime.h>
#include <cuda_bf16.h>
#include <cstdint>

#define N_NODES 50000
#define D_FEAT  64
#define H_FEAT  128

// Accumulator: overwritten by init each launch, so no cross-replay state.
__device__ float g_acc[(size_t)N_NODES * D_FEAT];

// ---- packed f32x2 helpers -------------------------------------------------
#define FMA2(d, a, b, c) \
    asm("fma.rn.f32x2 %0, %1, %2, %3;" : "=l"(d) : "l"(a), "l"(b), "l"(c))
#define PACK2(d, lo, hi) \
    asm("mov.b64 %0, {%1, %2};" : "=l"(d) : "f"(lo), "f"(hi))
#define UNPACK2(lo, hi, s) \
    asm("mov.b64 {%0, %1}, %2;" : "=f"(lo), "=f"(hi) : "l"(s))

#define RED4(addr, v) \
    asm volatile("red.global.add.v4.f32 [%0], {%1, %2, %3, %4};" \
                 :: "l"(addr), "f"((v).x), "f"((v).y), "f"((v).z), "f"((v).w) \
                 : "memory")

// ---------------------------------------------------------------------------
// Kernel 1: acc[i] = (1+eps) * x[i]   (R9-proven: 1 float4/thread)
// ---------------------------------------------------------------------------
__global__ void init_acc_kernel(const float* __restrict__ x,
                                const float* __restrict__ eps,
                                int total4) {
    int i = blockIdx.x * blockDim.x + threadIdx.x;
    if (i >= total4) return;
    float s = 1.0f + eps[0];
    float4 v = reinterpret_cast<const float4*>(x)[i];
    v.x *= s; v.y *= s; v.z *= s; v.w *= s;
    reinterpret_cast<float4*>(g_acc)[i] = v;
}

// ---------------------------------------------------------------------------
// Kernel 2: edge scatter, 4 lanes/edge, INTERLEAVED float4 chunks.
// Lane L handles chunks L, L+4, L+8, L+12: each red.v4 across the 4-lane
// group covers a contiguous 64B run (full-density sectors), and the 4 REDs
// tile the 256B row contiguously. Per-edge fixed overhead paid 4x not 8x.
// ---------------------------------------------------------------------------
__global__ void scatter_kernel(const float* __restrict__ x,
                               const int* __restrict__ ei,
                               int E, int N) {
    int t = blockIdx.x * blockDim.x + threadIdx.x;
    int e = t >> 2;
    if (e >= E) return;
    int q = (t & 3) << 2;    // float offset of first chunk: 0,4,8,12

    int s = ei[e];
    int d = ei[(size_t)E + e];
    if ((unsigned)s >= (unsigned)N || (unsigned)d >= (unsigned)N) return;

    const float* xs = x + (size_t)s * D_FEAT + q;
    const float* xd = x + (size_t)d * D_FEAT + q;
    float4 a0 = *reinterpret_cast<const float4*>(xs);
    float4 a1 = *reinterpret_cast<const float4*>(xs + 16);
    float4 a2 = *reinterpret_cast<const float4*>(xs + 32);
    float4 a3 = *reinterpret_cast<const float4*>(xs + 48);
    float4 b0 = *reinterpret_cast<const float4*>(xd);
    float4 b1 = *reinterpret_cast<const float4*>(xd + 16);
    float4 b2 = *reinterpret_cast<const float4*>(xd + 32);
    float4 b3 = *reinterpret_cast<const float4*>(xd + 48);

    float* as = g_acc + (size_t)s * D_FEAT + q;
    float* ad = g_acc + (size_t)d * D_FEAT + q;

    RED4(as,      b0);
    RED4(as + 16, b1);
    RED4(as + 32, b2);
    RED4(as + 48, b3);
    RED4(ad,      a0);
    RED4(ad + 16, a1);
    RED4(ad + 32, a2);
    RED4(ad + 48, a3);
}

// ---------------------------------------------------------------------------
// Kernel 3: fused GIN MLP (R9-exact): 64-node tiles, node-pair packed f32x2,
// compact weights (LDG.128 full-density), broadcast LDS.64 operands.
// ---------------------------------------------------------------------------
#define NT 64
#define VP 66   // even pitch -> all 64-bit smem accesses 8B-aligned

__global__ __launch_bounds__(256, 4)
void mlp_kernel(const float* __restrict__ W1, const float* __restrict__ b1,
                const float* __restrict__ W2, const float* __restrict__ b2,
                float* __restrict__ out, int N) {
    extern __shared__ float smem[];
    float* Vt = smem;                    // Vt[k][n]  64 x VP
    float* Ht = smem + D_FEAT * VP;      // Ht[j][n]  128 x VP

    const int t  = threadIdx.x;
    const int n0 = blockIdx.x * NT;

    // ---- stage V transposed from g_acc ----
    for (int idx = t; idx < NT * D_FEAT; idx += 256) {
        int n = idx >> 6;        // node in tile (0..63)
        int k = idx & 63;        // feature
        int node = n0 + n;
        Vt[k * VP + n] = (node < N) ? g_acc[(size_t)node * D_FEAT + k] : 0.0f;
    }
    __syncthreads();

    // ---- GEMM1: H[64][128] = relu(V @ W1 + b1) ----
    {
        const int tx = t & 31;       // 32 * 4 = 128 j-columns
        const int ty = t >> 5;       // 8 groups * 8 nodes = 64 nodes
        const int j4 = tx * 4;
        const int nb = ty * 8;

        unsigned long long a2[4][4];   // [node-pair p][col c]
        {
            float4 bb = *reinterpret_cast<const float4*>(b1 + j4);
            unsigned long long d0, d1, d2, d3;
            PACK2(d0, bb.x, bb.x); PACK2(d1, bb.y, bb.y);
            PACK2(d2, bb.z, bb.z); PACK2(d3, bb.w, bb.w);
            #pragma unroll
            for (int p = 0; p < 4; p++) {
                a2[p][0] = d0; a2[p][1] = d1; a2[p][2] = d2; a2[p][3] = d3;
            }
        }

        #pragma unroll 4
        for (int k = 0; k < D_FEAT; k++) {
            float4 w = *reinterpret_cast<const float4*>(W1 + k * H_FEAT + j4);
            unsigned long long w0, w1, w2, w3;
            PACK2(w0, w.x, w.x); PACK2(w1, w.y, w.y);
            PACK2(w2, w.z, w.z); PACK2(w3, w.w, w.w);
            const float* vrow = &Vt[k * VP + nb];
            unsigned long long v0 = *reinterpret_cast<const unsigned long long*>(vrow);
            unsigned long long v1 = *reinterpret_cast<const unsigned long long*>(vrow + 2);
            unsigned long long v2 = *reinterpret_cast<const unsigned long long*>(vrow + 4);
            unsigned long long v3 = *reinterpret_cast<const unsigned long long*>(vrow + 6);
            FMA2(a2[0][0], v0, w0, a2[0][0]); FMA2(a2[0][1], v0, w1, a2[0][1]);
            FMA2(a2[0][2], v0, w2, a2[0][2]); FMA2(a2[0][3], v0, w3, a2[0][3]);
            FMA2(a2[1][0], v1, w0, a2[1][0]); FMA2(a2[1][1], v1, w1, a2[1][1]);
            FMA2(a2[1][2], v1, w2, a2[1][2]); FMA2(a2[1][3], v1, w3, a2[1][3]);
            FMA2(a2[2][0], v2, w0, a2[2][0]); FMA2(a2[2][1], v2, w1, a2[2][1]);
            FMA2(a2[2][2], v2, w2, a2[2][2]); FMA2(a2[2][3], v2, w3, a2[2][3]);
            FMA2(a2[3][0], v3, w0, a2[3][0]); FMA2(a2[3][1], v3, w1, a2[3][1]);
            FMA2(a2[3][2], v3, w2, a2[3][2]); FMA2(a2[3][3], v3, w3, a2[3][3]);
        }

        #pragma unroll
        for (int c = 0; c < 4; c++) {
            #pragma unroll
            for (int p = 0; p < 4; p++) {
                float lo, hi;
                UNPACK2(lo, hi, a2[p][c]);
                lo = fmaxf(lo, 0.0f);
                hi = fmaxf(hi, 0.0f);
                unsigned long long pk; PACK2(pk, lo, hi);
                *reinterpret_cast<unsigned long long*>(
                    &Ht[(j4 + c) * VP + nb + 2 * p]) = pk;
            }
        }
    }
    __syncthreads();

    // ---- GEMM2: Y[64][64] = H @ W2 + b2 ----
    {
        const int tx = t & 15;       // 16 * 4 = 64 d-columns
        const int ty = t >> 4;       // 16 groups * 4 nodes = 64 nodes
        const int d4 = tx * 4;
        const int nb = ty * 4;

        unsigned long long a2[2][4];   // [node-pair q][col c]
        {
            float4 bb = *reinterpret_cast<const float4*>(b2 + d4);
            unsigned long long d0, d1, d2, d3;
            PACK2(d0, bb.x, bb.x); PACK2(d1, bb.y, bb.y);
            PACK2(d2, bb.z, bb.z); PACK2(d3, bb.w, bb.w);
            a2[0][0] = d0; a2[0][1] = d1; a2[0][2] = d2; a2[0][3] = d3;
            a2[1][0] = d0; a2[1][1] = d1; a2[1][2] = d2; a2[1][3] = d3;
        }

        #pragma unroll 4
        for (int j = 0; j < H_FEAT; j++) {
            float4 w = *reinterpret_cast<const float4*>(W2 + j * D_FEAT + d4);
            unsigned long long w0, w1, w2, w3;
            PACK2(w0, w.x, w.x); PACK2(w1, w.y, w.y);
            PACK2(w2, w.z, w.z); PACK2(w3, w.w, w.w);
            const float* hrow = &Ht[j * VP + nb];
            unsigned long long h0 = *reinterpret_cast<const unsigned long long*>(hrow);
            unsigned long long h1 = *reinterpret_cast<const unsigned long long*>(hrow + 2);
            FMA2(a2[0][0], h0, w0, a2[0][0]); FMA2(a2[0][1], h0, w1, a2[0][1]);
            FMA2(a2[0][2], h0, w2, a2[0][2]); FMA2(a2[0][3], h0, w3, a2[0][3]);
            FMA2(a2[1][0], h1, w0, a2[1][0]); FMA2(a2[1][1], h1, w1, a2[1][1]);
            FMA2(a2[1][2], h1, w2, a2[1][2]); FMA2(a2[1][3], h1, w3, a2[1][3]);
        }

        #pragma unroll
        for (int q = 0; q < 2; q++) {
            float l0, h0, l1, h1, l2, h2, l3, h3;
            UNPACK2(l0, h0, a2[q][0]);
            UNPACK2(l1, h1, a2[q][1]);
            UNPACK2(l2, h2, a2[q][2]);
            UNPACK2(l3, h3, a2[q][3]);
            int node0 = n0 + nb + 2 * q;
            if (node0 < N)
                *reinterpret_cast<float4*>(out + (size_t)node0 * D_FEAT + d4) =
                    make_float4(l0, l1, l2, l3);
            if (node0 + 1 < N)
                *reinterpret_cast<float4*>(out + (size_t)(node0 + 1) * D_FEAT + d4) =
                    make_float4(h0, h1, h2, h3);
        }
    }
}

// ---------------------------------------------------------------------------
// Launch
// ---------------------------------------------------------------------------
extern "C" void kernel_launch(void* const* d_in, const int* in_sizes, int n_in,
                              void* d_out, int out_size) {
    const float* x   = (const float*)d_in[0];
    const float* W1  = (const float*)d_in[1];
    const float* b1  = (const float*)d_in[2];
    const float* W2  = (const float*)d_in[3];
    const float* b2  = (const float*)d_in[4];
    const float* eps = (const float*)d_in[5];
    const int*   ei  = (const int*)d_in[6];
    float* out = (float*)d_out;

    const int N = in_sizes[0] / D_FEAT;     // 50000
    const int E = in_sizes[6] / 2;          // 800000

    const int smem_bytes = (D_FEAT + H_FEAT) * VP * (int)sizeof(float); // 50688
    static int attr_set = 0;
    if (!attr_set) {
        cudaFuncSetAttribute(mlp_kernel,
                             cudaFuncAttributeMaxDynamicSharedMemorySize,
                             smem_bytes);
        attr_set = 1;
    }

    // 1) acc = (1+eps)*x
    int total4 = N * D_FEAT / 4;
    init_acc_kernel<<<(total4 + 255) / 256, 256>>>(x, eps, total4);

    // 2) edge scatter (4 lanes/edge, interleaved float4 chunks)
    long long threads = (long long)E * 4;
    int blocks = (int)((threads + 255) / 256);
    scatter_kernel<<<blocks, 256>>>(x, ei, E, N);

    // 3) fused MLP (64-node tiles)
    mlp_kernel<<<(N + NT - 1) / NT, 256, smem_bytes>>>(W1, b1, W2, b2, out, N);
}

// round 13
// speedup vs baseline: 1.1384x; 1.1384x over previous
#include <cuda_runtime.h>
#include <cuda_bf16.h>
#include <cstdint>

#define N_NODES 50000
#define D_FEAT  64
#define H_FEAT  128

// Accumulator: overwritten by init each launch, so no cross-replay state.
__device__ float g_acc[(size_t)N_NODES * D_FEAT];

// ---- packed f32x2 helpers -------------------------------------------------
#define FMA2(d, a, b, c) \
    asm("fma.rn.f32x2 %0, %1, %2, %3;" : "=l"(d) : "l"(a), "l"(b), "l"(c))
#define PACK2(d, lo, hi) \
    asm("mov.b64 %0, {%1, %2};" : "=l"(d) : "f"(lo), "f"(hi))
#define UNPACK2(lo, hi, s) \
    asm("mov.b64 {%0, %1}, %2;" : "=f"(lo), "=f"(hi) : "l"(s))

#define RED4(addr, v) \
    asm volatile("red.global.add.v4.f32 [%0], {%1, %2, %3, %4};" \
                 :: "l"(addr), "f"((v).x), "f"((v).y), "f"((v).z), "f"((v).w) \
                 : "memory")

// ---------------------------------------------------------------------------
// Kernel 1: acc[i] = (1+eps) * x[i]   (R9-proven: 1 float4/thread)
// ---------------------------------------------------------------------------
__global__ void init_acc_kernel(const float* __restrict__ x,
                                const float* __restrict__ eps,
                                int total4) {
    int i = blockIdx.x * blockDim.x + threadIdx.x;
    if (i >= total4) return;
    float s = 1.0f + eps[0];
    float4 v = reinterpret_cast<const float4*>(x)[i];
    v.x *= s; v.y *= s; v.z *= s; v.w *= s;
    reinterpret_cast<float4*>(g_acc)[i] = v;
}

// ---------------------------------------------------------------------------
// Kernel 2: edge scatter. 8 lanes/edge, INTERLEAVED float4 chunks (lane L
// handles chunks L and L+8 -> each red.v4 across the 8-lane group covers one
// full 128B line). Each thread processes TWO edges (e and e+halfE) to halve
// per-thread fixed costs and deepen MLP.
// ---------------------------------------------------------------------------
__device__ __forceinline__ void scatter_one(const float* __restrict__ x,
                                            const int* __restrict__ ei,
                                            int e, int q, int E, int N) {
    int s = ei[e];
    int d = ei[(size_t)E + e];
    if ((unsigned)s >= (unsigned)N || (unsigned)d >= (unsigned)N) return;

    const float* xs = x + (size_t)s * D_FEAT + q;
    const float* xd = x + (size_t)d * D_FEAT + q;
    float4 a0 = *reinterpret_cast<const float4*>(xs);
    float4 a1 = *reinterpret_cast<const float4*>(xs + 32);
    float4 b0 = *reinterpret_cast<const float4*>(xd);
    float4 b1 = *reinterpret_cast<const float4*>(xd + 32);

    float* as = g_acc + (size_t)s * D_FEAT + q;
    float* ad = g_acc + (size_t)d * D_FEAT + q;

    RED4(as,      b0);
    RED4(as + 32, b1);
    RED4(ad,      a0);
    RED4(ad + 32, a1);
}

__global__ void scatter_kernel(const float* __restrict__ x,
                               const int* __restrict__ ei,
                               int E, int halfE, int N) {
    int t = blockIdx.x * blockDim.x + threadIdx.x;
    int e = t >> 3;
    if (e >= halfE) return;
    int q = (t & 7) << 2;    // float offset of first chunk: 0,4,...,28

    scatter_one(x, ei, e, q, E, N);
    int e2 = e + halfE;
    if (e2 < E) scatter_one(x, ei, e2, q, E, N);
}

// ---------------------------------------------------------------------------
// Kernel 3: fused GIN MLP (R9-exact): 64-node tiles, node-pair packed f32x2,
// compact weights (LDG.128 full-density), broadcast LDS.64 operands.
// ---------------------------------------------------------------------------
#define NT 64
#define VP 66   // even pitch -> all 64-bit smem accesses 8B-aligned

__global__ __launch_bounds__(256, 4)
void mlp_kernel(const float* __restrict__ W1, const float* __restrict__ b1,
                const float* __restrict__ W2, const float* __restrict__ b2,
                float* __restrict__ out, int N) {
    extern __shared__ float smem[];
    float* Vt = smem;                    // Vt[k][n]  64 x VP
    float* Ht = smem + D_FEAT * VP;      // Ht[j][n]  128 x VP

    const int t  = threadIdx.x;
    const int n0 = blockIdx.x * NT;

    // ---- stage V transposed from g_acc ----
    for (int idx = t; idx < NT * D_FEAT; idx += 256) {
        int n = idx >> 6;        // node in tile (0..63)
        int k = idx & 63;        // feature
        int node = n0 + n;
        Vt[k * VP + n] = (node < N) ? g_acc[(size_t)node * D_FEAT + k] : 0.0f;
    }
    __syncthreads();

    // ---- GEMM1: H[64][128] = relu(V @ W1 + b1) ----
    {
        const int tx = t & 31;       // 32 * 4 = 128 j-columns
        const int ty = t >> 5;       // 8 groups * 8 nodes = 64 nodes
        const int j4 = tx * 4;
        const int nb = ty * 8;

        unsigned long long a2[4][4];   // [node-pair p][col c]
        {
            float4 bb = *reinterpret_cast<const float4*>(b1 + j4);
            unsigned long long d0, d1, d2, d3;
            PACK2(d0, bb.x, bb.x); PACK2(d1, bb.y, bb.y);
            PACK2(d2, bb.z, bb.z); PACK2(d3, bb.w, bb.w);
            #pragma unroll
            for (int p = 0; p < 4; p++) {
                a2[p][0] = d0; a2[p][1] = d1; a2[p][2] = d2; a2[p][3] = d3;
            }
        }

        #pragma unroll 4
        for (int k = 0; k < D_FEAT; k++) {
            float4 w = *reinterpret_cast<const float4*>(W1 + k * H_FEAT + j4);
            unsigned long long w0, w1, w2, w3;
            PACK2(w0, w.x, w.x); PACK2(w1, w.y, w.y);
            PACK2(w2, w.z, w.z); PACK2(w3, w.w, w.w);
            const float* vrow = &Vt[k * VP + nb];
            unsigned long long v0 = *reinterpret_cast<const unsigned long long*>(vrow);
            unsigned long long v1 = *reinterpret_cast<const unsigned long long*>(vrow + 2);
            unsigned long long v2 = *reinterpret_cast<const unsigned long long*>(vrow + 4);
            unsigned long long v3 = *reinterpret_cast<const unsigned long long*>(vrow + 6);
            FMA2(a2[0][0], v0, w0, a2[0][0]); FMA2(a2[0][1], v0, w1, a2[0][1]);
            FMA2(a2[0][2], v0, w2, a2[0][2]); FMA2(a2[0][3], v0, w3, a2[0][3]);
            FMA2(a2[1][0], v1, w0, a2[1][0]); FMA2(a2[1][1], v1, w1, a2[1][1]);
            FMA2(a2[1][2], v1, w2, a2[1][2]); FMA2(a2[1][3], v1, w3, a2[1][3]);
            FMA2(a2[2][0], v2, w0, a2[2][0]); FMA2(a2[2][1], v2, w1, a2[2][1]);
            FMA2(a2[2][2], v2, w2, a2[2][2]); FMA2(a2[2][3], v2, w3, a2[2][3]);
            FMA2(a2[3][0], v3, w0, a2[3][0]); FMA2(a2[3][1], v3, w1, a2[3][1]);
            FMA2(a2[3][2], v3, w2, a2[3][2]); FMA2(a2[3][3], v3, w3, a2[3][3]);
        }

        #pragma unroll
        for (int c = 0; c < 4; c++) {
            #pragma unroll
            for (int p = 0; p < 4; p++) {
                float lo, hi;
                UNPACK2(lo, hi, a2[p][c]);
                lo = fmaxf(lo, 0.0f);
                hi = fmaxf(hi, 0.0f);
                unsigned long long pk; PACK2(pk, lo, hi);
                *reinterpret_cast<unsigned long long*>(
                    &Ht[(j4 + c) * VP + nb + 2 * p]) = pk;
            }
        }
    }
    __syncthreads();

    // ---- GEMM2: Y[64][64] = H @ W2 + b2 ----
    {
        const int tx = t & 15;       // 16 * 4 = 64 d-columns
        const int ty = t >> 4;       // 16 groups * 4 nodes = 64 nodes
        const int d4 = tx * 4;
        const int nb = ty * 4;

        unsigned long long a2[2][4];   // [node-pair q][col c]
        {
            float4 bb = *reinterpret_cast<const float4*>(b2 + d4);
            unsigned long long d0, d1, d2, d3;
            PACK2(d0, bb.x, bb.x); PACK2(d1, bb.y, bb.y);
            PACK2(d2, bb.z, bb.z); PACK2(d3, bb.w, bb.w);
            a2[0][0] = d0; a2[0][1] = d1; a2[0][2] = d2; a2[0][3] = d3;
            a2[1][0] = d0; a2[1][1] = d1; a2[1][2] = d2; a2[1][3] = d3;
        }

        #pragma unroll 4
        for (int j = 0; j < H_FEAT; j++) {
            float4 w = *reinterpret_cast<const float4*>(W2 + j * D_FEAT + d4);
            unsigned long long w0, w1, w2, w3;
            PACK2(w0, w.x, w.x); PACK2(w1, w.y, w.y);
            PACK2(w2, w.z, w.z); PACK2(w3, w.w, w.w);
            const float* hrow = &Ht[j * VP + nb];
            unsigned long long h0 = *reinterpret_cast<const unsigned long long*>(hrow);
            unsigned long long h1 = *reinterpret_cast<const unsigned long long*>(hrow + 2);
            FMA2(a2[0][0], h0, w0, a2[0][0]); FMA2(a2[0][1], h0, w1, a2[0][1]);
            FMA2(a2[0][2], h0, w2, a2[0][2]); FMA2(a2[0][3], h0, w3, a2[0][3]);
            FMA2(a2[1][0], h1, w0, a2[1][0]); FMA2(a2[1][1], h1, w1, a2[1][1]);
            FMA2(a2[1][2], h1, w2, a2[1][2]); FMA2(a2[1][3], h1, w3, a2[1][3]);
        }

        #pragma unroll
        for (int q = 0; q < 2; q++) {
            float l0, h0, l1, h1, l2, h2, l3, h3;
            UNPACK2(l0, h0, a2[q][0]);
            UNPACK2(l1, h1, a2[q][1]);
            UNPACK2(l2, h2, a2[q][2]);
            UNPACK2(l3, h3, a2[q][3]);
            int node0 = n0 + nb + 2 * q;
            if (node0 < N)
                *reinterpret_cast<float4*>(out + (size_t)node0 * D_FEAT + d4) =
                    make_float4(l0, l1, l2, l3);
            if (node0 + 1 < N)
                *reinterpret_cast<float4*>(out + (size_t)(node0 + 1) * D_FEAT + d4) =
                    make_float4(h0, h1, h2, h3);
        }
    }
}

// ---------------------------------------------------------------------------
// Launch
// ---------------------------------------------------------------------------
extern "C" void kernel_launch(void* const* d_in, const int* in_sizes, int n_in,
                              void* d_out, int out_size) {
    const float* x   = (const float*)d_in[0];
    const float* W1  = (const float*)d_in[1];
    const float* b1  = (const float*)d_in[2];
    const float* W2  = (const float*)d_in[3];
    const float* b2  = (const float*)d_in[4];
    const float* eps = (const float*)d_in[5];
    const int*   ei  = (const int*)d_in[6];
    float* out = (float*)d_out;

    const int N = in_sizes[0] / D_FEAT;     // 50000
    const int E = in_sizes[6] / 2;          // 800000

    const int smem_bytes = (D_FEAT + H_FEAT) * VP * (int)sizeof(float); // 50688
    static int attr_set = 0;
    if (!attr_set) {
        cudaFuncSetAttribute(mlp_kernel,
                             cudaFuncAttributeMaxDynamicSharedMemorySize,
                             smem_bytes);
        attr_set = 1;
    }

    // 1) acc = (1+eps)*x
    int total4 = N * D_FEAT / 4;
    init_acc_kernel<<<(total4 + 255) / 256, 256>>>(x, eps, total4);

    // 2) edge scatter (8 lanes/edge interleaved, 2 edges/thread)
    int halfE = (E + 1) / 2;
    long long threads = (long long)halfE * 8;
    int blocks = (int)((threads + 255) / 256);
    scatter_kernel<<<blocks, 256>>>(x, ei, E, halfE, N);

    // 3) fused MLP (64-node tiles)
    mlp_kernel<<<(N + NT - 1) / NT, 256, smem_bytes>>>(W1, b1, W2, b2, out, N);
}

// round 14
// speedup vs baseline: 1.1580x; 1.0172x over previous
#include <cuda_runtime.h>
#include <cuda_bf16.h>
#include <cstdint>

#define N_NODES 50000
#define D_FEAT  64
#define H_FEAT  128

// Accumulator: overwritten by init each launch, so no cross-replay state.
__device__ float g_acc[(size_t)N_NODES * D_FEAT];

// ---- packed f32x2 helpers -------------------------------------------------
#define FMA2(d, a, b, c) \
    asm("fma.rn.f32x2 %0, %1, %2, %3;" : "=l"(d) : "l"(a), "l"(b), "l"(c))
#define PACK2(d, lo, hi) \
    asm("mov.b64 %0, {%1, %2};" : "=l"(d) : "f"(lo), "f"(hi))
#define UNPACK2(lo, hi, s) \
    asm("mov.b64 {%0, %1}, %2;" : "=f"(lo), "=f"(hi) : "l"(s))

#define RED4(addr, v) \
    asm volatile("red.global.add.v4.f32 [%0], {%1, %2, %3, %4};" \
                 :: "l"(addr), "f"((v).x), "f"((v).y), "f"((v).z), "f"((v).w) \
                 : "memory")

// ---------------------------------------------------------------------------
// Kernel 1: acc[i] = (1+eps) * x[i]   (1 float4/thread; proven 6.8us)
// ---------------------------------------------------------------------------
__global__ void init_acc_kernel(const float* __restrict__ x,
                                const float* __restrict__ eps,
                                int total4) {
    int i = blockIdx.x * blockDim.x + threadIdx.x;
    if (i >= total4) return;
    float s = 1.0f + eps[0];
    float4 v = reinterpret_cast<const float4*>(x)[i];
    v.x *= s; v.y *= s; v.z *= s; v.w *= s;
    reinterpret_cast<float4*>(g_acc)[i] = v;
}

// ---------------------------------------------------------------------------
// Kernel 2: edge scatter, 8 lanes/edge, INTERLEAVED float4 chunks.
// Lane L handles chunks L and L+8, so each red.v4 across the 8-lane group
// covers one contiguous 128B line (full-density L2 wavefronts), while
// per-edge fixed overhead (index loads, guards, addressing) is paid 8x not 16x.
// This is the measured optimum of the lane-layout family (16/8/4-lane,
// 2-edge coarsening all tested). At the L2-RMW roofline (~100us).
// ---------------------------------------------------------------------------
__global__ void scatter_kernel(const float* __restrict__ x,
                               const int* __restrict__ ei,
                               int E, int N) {
    int t = blockIdx.x * blockDim.x + threadIdx.x;
    int e = t >> 3;
    if (e >= E) return;
    int q = (t & 7) << 2;    // float offset of first chunk: 0,4,...,28

    int s = ei[e];
    int d = ei[(size_t)E + e];
    if ((unsigned)s >= (unsigned)N || (unsigned)d >= (unsigned)N) return;

    const float* xs = x + (size_t)s * D_FEAT + q;
    const float* xd = x + (size_t)d * D_FEAT + q;
    float4 a0 = *reinterpret_cast<const float4*>(xs);
    float4 a1 = *reinterpret_cast<const float4*>(xs + 32);
    float4 b0 = *reinterpret_cast<const float4*>(xd);
    float4 b1 = *reinterpret_cast<const float4*>(xd + 32);

    float* as = g_acc + (size_t)s * D_FEAT + q;
    float* ad = g_acc + (size_t)d * D_FEAT + q;

    RED4(as,      b0);
    RED4(as + 32, b1);
    RED4(ad,      a0);
    RED4(ad + 32, a1);
}

// ---------------------------------------------------------------------------
// Kernel 3: fused GIN MLP: 64-node tiles, node-pair packed f32x2,
// compact weights (LDG.128 full-density), broadcast LDS.64 operands.
// ---------------------------------------------------------------------------
#define NT 64
#define VP 66   // even pitch -> all 64-bit smem accesses 8B-aligned

__global__ __launch_bounds__(256, 4)
void mlp_kernel(const float* __restrict__ W1, const float* __restrict__ b1,
                const float* __restrict__ W2, const float* __restrict__ b2,
                float* __restrict__ out, int N) {
    extern __shared__ float smem[];
    float* Vt = smem;                    // Vt[k][n]  64 x VP
    float* Ht = smem + D_FEAT * VP;      // Ht[j][n]  128 x VP

    const int t  = threadIdx.x;
    const int n0 = blockIdx.x * NT;

    // ---- stage V transposed from g_acc ----
    for (int idx = t; idx < NT * D_FEAT; idx += 256) {
        int n = idx >> 6;        // node in tile (0..63)
        int k = idx & 63;        // feature
        int node = n0 + n;
        Vt[k * VP + n] = (node < N) ? g_acc[(size_t)node * D_FEAT + k] : 0.0f;
    }
    __syncthreads();

    // ---- GEMM1: H[64][128] = relu(V @ W1 + b1) ----
    {
        const int tx = t & 31;       // 32 * 4 = 128 j-columns
        const int ty = t >> 5;       // 8 groups * 8 nodes = 64 nodes
        const int j4 = tx * 4;
        const int nb = ty * 8;

        unsigned long long a2[4][4];   // [node-pair p][col c]
        {
            float4 bb = *reinterpret_cast<const float4*>(b1 + j4);
            unsigned long long d0, d1, d2, d3;
            PACK2(d0, bb.x, bb.x); PACK2(d1, bb.y, bb.y);
            PACK2(d2, bb.z, bb.z); PACK2(d3, bb.w, bb.w);
            #pragma unroll
            for (int p = 0; p < 4; p++) {
                a2[p][0] = d0; a2[p][1] = d1; a2[p][2] = d2; a2[p][3] = d3;
            }
        }

        #pragma unroll 4
        for (int k = 0; k < D_FEAT; k++) {
            float4 w = *reinterpret_cast<const float4*>(W1 + k * H_FEAT + j4);
            unsigned long long w0, w1, w2, w3;
            PACK2(w0, w.x, w.x); PACK2(w1, w.y, w.y);
            PACK2(w2, w.z, w.z); PACK2(w3, w.w, w.w);
            const float* vrow = &Vt[k * VP + nb];
            unsigned long long v0 = *reinterpret_cast<const unsigned long long*>(vrow);
            unsigned long long v1 = *reinterpret_cast<const unsigned long long*>(vrow + 2);
            unsigned long long v2 = *reinterpret_cast<const unsigned long long*>(vrow + 4);
            unsigned long long v3 = *reinterpret_cast<const unsigned long long*>(vrow + 6);
            FMA2(a2[0][0], v0, w0, a2[0][0]); FMA2(a2[0][1], v0, w1, a2[0][1]);
            FMA2(a2[0][2], v0, w2, a2[0][2]); FMA2(a2[0][3], v0, w3, a2[0][3]);
            FMA2(a2[1][0], v1, w0, a2[1][0]); FMA2(a2[1][1], v1, w1, a2[1][1]);
            FMA2(a2[1][2], v1, w2, a2[1][2]); FMA2(a2[1][3], v1, w3, a2[1][3]);
            FMA2(a2[2][0], v2, w0, a2[2][0]); FMA2(a2[2][1], v2, w1, a2[2][1]);
            FMA2(a2[2][2], v2, w2, a2[2][2]); FMA2(a2[2][3], v2, w3, a2[2][3]);
            FMA2(a2[3][0], v3, w0, a2[3][0]); FMA2(a2[3][1], v3, w1, a2[3][1]);
            FMA2(a2[3][2], v3, w2, a2[3][2]); FMA2(a2[3][3], v3, w3, a2[3][3]);
        }

        #pragma unroll
        for (int c = 0; c < 4; c++) {
            #pragma unroll
            for (int p = 0; p < 4; p++) {
                float lo, hi;
                UNPACK2(lo, hi, a2[p][c]);
                lo = fmaxf(lo, 0.0f);
                hi = fmaxf(hi, 0.0f);
                unsigned long long pk; PACK2(pk, lo, hi);
                *reinterpret_cast<unsigned long long*>(
                    &Ht[(j4 + c) * VP + nb + 2 * p]) = pk;
            }
        }
    }
    __syncthreads();

    // ---- GEMM2: Y[64][64] = H @ W2 + b2 ----
    {
        const int tx = t & 15;       // 16 * 4 = 64 d-columns
        const int ty = t >> 4;       // 16 groups * 4 nodes = 64 nodes
        const int d4 = tx * 4;
        const int nb = ty * 4;

        unsigned long long a2[2][4];   // [node-pair q][col c]
        {
            float4 bb = *reinterpret_cast<const float4*>(b2 + d4);
            unsigned long long d0, d1, d2, d3;
            PACK2(d0, bb.x, bb.x); PACK2(d1, bb.y, bb.y);
            PACK2(d2, bb.z, bb.z); PACK2(d3, bb.w, bb.w);
            a2[0][0] = d0; a2[0][1] = d1; a2[0][2] = d2; a2[0][3] = d3;
            a2[1][0] = d0; a2[1][1] = d1; a2[1][2] = d2; a2[1][3] = d3;
        }

        #pragma unroll 4
        for (int j = 0; j < H_FEAT; j++) {
            float4 w = *reinterpret_cast<const float4*>(W2 + j * D_FEAT + d4);
            unsigned long long w0, w1, w2, w3;
            PACK2(w0, w.x, w.x); PACK2(w1, w.y, w.y);
            PACK2(w2, w.z, w.z); PACK2(w3, w.w, w.w);
            const float* hrow = &Ht[j * VP + nb];
            unsigned long long h0 = *reinterpret_cast<const unsigned long long*>(hrow);
            unsigned long long h1 = *reinterpret_cast<const unsigned long long*>(hrow + 2);
            FMA2(a2[0][0], h0, w0, a2[0][0]); FMA2(a2[0][1], h0, w1, a2[0][1]);
            FMA2(a2[0][2], h0, w2, a2[0][2]); FMA2(a2[0][3], h0, w3, a2[0][3]);
            FMA2(a2[1][0], h1, w0, a2[1][0]); FMA2(a2[1][1], h1, w1, a2[1][1]);
            FMA2(a2[1][2], h1, w2, a2[1][2]); FMA2(a2[1][3], h1, w3, a2[1][3]);
        }

        #pragma unroll
        for (int q = 0; q < 2; q++) {
            float l0, h0, l1, h1, l2, h2, l3, h3;
            UNPACK2(l0, h0, a2[q][0]);
            UNPACK2(l1, h1, a2[q][1]);
            UNPACK2(l2, h2, a2[q][2]);
            UNPACK2(l3, h3, a2[q][3]);
            int node0 = n0 + nb + 2 * q;
            if (node0 < N)
                *reinterpret_cast<float4*>(out + (size_t)node0 * D_FEAT + d4) =
                    make_float4(l0, l1, l2, l3);
            if (node0 + 1 < N)
                *reinterpret_cast<float4*>(out + (size_t)(node0 + 1) * D_FEAT + d4) =
                    make_float4(h0, h1, h2, h3);
        }
    }
}

// ---------------------------------------------------------------------------
// Launch
// ---------------------------------------------------------------------------
extern "C" void kernel_launch(void* const* d_in, const int* in_sizes, int n_in,
                              void* d_out, int out_size) {
    const float* x   = (const float*)d_in[0];
    const float* W1  = (const float*)d_in[1];
    const float* b1  = (const float*)d_in[2];
    const float* W2  = (const float*)d_in[3];
    const float* b2  = (const float*)d_in[4];
    const float* eps = (const float*)d_in[5];
    const int*   ei  = (const int*)d_in[6];
    float* out = (float*)d_out;

    const int N = in_sizes[0] / D_FEAT;     // 50000
    const int E = in_sizes[6] / 2;          // 800000

    const int smem_bytes = (D_FEAT + H_FEAT) * VP * (int)sizeof(float); // 50688
    static int attr_set = 0;
    if (!attr_set) {
        cudaFuncSetAttribute(mlp_kernel,
                             cudaFuncAttributeMaxDynamicSharedMemorySize,
                             smem_bytes);
        attr_set = 1;
    }

    // 1) acc = (1+eps)*x
    int total4 = N * D_FEAT / 4;
    init_acc_kernel<<<(total4 + 255) / 256, 256>>>(x, eps, total4);

    // 2) edge scatter (8 lanes/edge, interleaved float4 chunks)
    long long threads = (long long)E * 8;
    int blocks = (int)((threads + 255) / 256);
    scatter_kernel<<<blocks, 256>>>(x, ei, E, N);

    // 3) fused MLP (64-node tiles)
    mlp_kernel<<<(N + NT - 1) / NT, 256, smem_bytes>>>(W1, b1, W2, b2, out, N);
}

// round 15
// speedup vs baseline: 1.1586x; 1.0005x over previous
#include <cuda_runtime.h>
#include <cuda_bf16.h>
#include <cstdint>

#define N_NODES 50000
#define D_FEAT  64
#define H_FEAT  128

// Accumulator: overwritten by init each launch, so no cross-replay state.
__device__ float g_acc[(size_t)N_NODES * D_FEAT];

// ---- packed f32x2 helpers -------------------------------------------------
#define FMA2(d, a, b, c) \
    asm("fma.rn.f32x2 %0, %1, %2, %3;" : "=l"(d) : "l"(a), "l"(b), "l"(c))
#define PACK2(d, lo, hi) \
    asm("mov.b64 %0, {%1, %2};" : "=l"(d) : "f"(lo), "f"(hi))
#define UNPACK2(lo, hi, s) \
    asm("mov.b64 {%0, %1}, %2;" : "=f"(lo), "=f"(hi) : "l"(s))

#define RED4(addr, v) \
    asm volatile("red.global.add.v4.f32 [%0], {%1, %2, %3, %4};" \
                 :: "l"(addr), "f"((v).x), "f"((v).y), "f"((v).z), "f"((v).w) \
                 : "memory")

// 128-bit global load, non-coherent, no L1 allocation (one-touch gather data)
#define LDG128_NA(v, p) \
    asm volatile("ld.global.nc.L1::no_allocate.v4.f32 {%0, %1, %2, %3}, [%4];" \
                 : "=f"((v).x), "=f"((v).y), "=f"((v).z), "=f"((v).w) : "l"(p))

// ---------------------------------------------------------------------------
// Kernel 1: acc[i] = (1+eps) * x[i]   (1 float4/thread; proven 6.7us)
// ---------------------------------------------------------------------------
__global__ void init_acc_kernel(const float* __restrict__ x,
                                const float* __restrict__ eps,
                                int total4) {
    int i = blockIdx.x * blockDim.x + threadIdx.x;
    if (i >= total4) return;
    float s = 1.0f + eps[0];
    float4 v = reinterpret_cast<const float4*>(x)[i];
    v.x *= s; v.y *= s; v.z *= s; v.w *= s;
    reinterpret_cast<float4*>(g_acc)[i] = v;
}

// ---------------------------------------------------------------------------
// Kernel 2: edge scatter, 8 lanes/edge, INTERLEAVED float4 chunks.
// Lane L handles chunks L and L+8, so each red.v4 across the 8-lane group
// covers one contiguous 128B line (full-density L2 wavefronts), while
// per-edge fixed overhead is paid 8x not 16x. Gathers skip L1 allocation
// (reuse ~1.8%, one-touch). Measured optimum of the lane-layout family.
// ---------------------------------------------------------------------------
__global__ void scatter_kernel(const float* __restrict__ x,
                               const int* __restrict__ ei,
                               int E, int N) {
    int t = blockIdx.x * blockDim.x + threadIdx.x;
    int e = t >> 3;
    if (e >= E) return;
    int q = (t & 7) << 2;    // float offset of first chunk: 0,4,...,28

    int s = __ldg(ei + e);
    int d = __ldg(ei + (size_t)E + e);
    if ((unsigned)s >= (unsigned)N || (unsigned)d >= (unsigned)N) return;

    const float* xs = x + (size_t)s * D_FEAT + q;
    const float* xd = x + (size_t)d * D_FEAT + q;
    float4 a0, a1, b0, b1;
    LDG128_NA(a0, xs);
    LDG128_NA(a1, xs + 32);
    LDG128_NA(b0, xd);
    LDG128_NA(b1, xd + 32);

    float* as = g_acc + (size_t)s * D_FEAT + q;
    float* ad = g_acc + (size_t)d * D_FEAT + q;

    RED4(as,      b0);
    RED4(as + 32, b1);
    RED4(ad,      a0);
    RED4(ad + 32, a1);
}

// ---------------------------------------------------------------------------
// Kernel 3: fused GIN MLP: 64-node tiles, node-pair packed f32x2,
// compact weights (LDG.128 full-density), broadcast LDS.64 operands.
// ---------------------------------------------------------------------------
#define NT 64
#define VP 66   // even pitch -> all 64-bit smem accesses 8B-aligned

__global__ __launch_bounds__(256, 4)
void mlp_kernel(const float* __restrict__ W1, const float* __restrict__ b1,
                const float* __restrict__ W2, const float* __restrict__ b2,
                float* __restrict__ out, int N) {
    extern __shared__ float smem[];
    float* Vt = smem;                    // Vt[k][n]  64 x VP
    float* Ht = smem + D_FEAT * VP;      // Ht[j][n]  128 x VP

    const int t  = threadIdx.x;
    const int n0 = blockIdx.x * NT;

    // ---- stage V transposed from g_acc ----
    for (int idx = t; idx < NT * D_FEAT; idx += 256) {
        int n = idx >> 6;        // node in tile (0..63)
        int k = idx & 63;        // feature
        int node = n0 + n;
        Vt[k * VP + n] = (node < N) ? g_acc[(size_t)node * D_FEAT + k] : 0.0f;
    }
    __syncthreads();

    // ---- GEMM1: H[64][128] = relu(V @ W1 + b1) ----
    {
        const int tx = t & 31;       // 32 * 4 = 128 j-columns
        const int ty = t >> 5;       // 8 groups * 8 nodes = 64 nodes
        const int j4 = tx * 4;
        const int nb = ty * 8;

        unsigned long long a2[4][4];   // [node-pair p][col c]
        {
            float4 bb = *reinterpret_cast<const float4*>(b1 + j4);
            unsigned long long d0, d1, d2, d3;
            PACK2(d0, bb.x, bb.x); PACK2(d1, bb.y, bb.y);
            PACK2(d2, bb.z, bb.z); PACK2(d3, bb.w, bb.w);
            #pragma unroll
            for (int p = 0; p < 4; p++) {
                a2[p][0] = d0; a2[p][1] = d1; a2[p][2] = d2; a2[p][3] = d3;
            }
        }

        #pragma unroll 4
        for (int k = 0; k < D_FEAT; k++) {
            float4 w = *reinterpret_cast<const float4*>(W1 + k * H_FEAT + j4);
            unsigned long long w0, w1, w2, w3;
            PACK2(w0, w.x, w.x); PACK2(w1, w.y, w.y);
            PACK2(w2, w.z, w.z); PACK2(w3, w.w, w.w);
            const float* vrow = &Vt[k * VP + nb];
            unsigned long long v0 = *reinterpret_cast<const unsigned long long*>(vrow);
            unsigned long long v1 = *reinterpret_cast<const unsigned long long*>(vrow + 2);
            unsigned long long v2 = *reinterpret_cast<const unsigned long long*>(vrow + 4);
            unsigned long long v3 = *reinterpret_cast<const unsigned long long*>(vrow + 6);
            FMA2(a2[0][0], v0, w0, a2[0][0]); FMA2(a2[0][1], v0, w1, a2[0][1]);
            FMA2(a2[0][2], v0, w2, a2[0][2]); FMA2(a2[0][3], v0, w3, a2[0][3]);
            FMA2(a2[1][0], v1, w0, a2[1][0]); FMA2(a2[1][1], v1, w1, a2[1][1]);
            FMA2(a2[1][2], v1, w2, a2[1][2]); FMA2(a2[1][3], v1, w3, a2[1][3]);
            FMA2(a2[2][0], v2, w0, a2[2][0]); FMA2(a2[2][1], v2, w1, a2[2][1]);
            FMA2(a2[2][2], v2, w2, a2[2][2]); FMA2(a2[2][3], v2, w3, a2[2][3]);
            FMA2(a2[3][0], v3, w0, a2[3][0]); FMA2(a2[3][1], v3, w1, a2[3][1]);
            FMA2(a2[3][2], v3, w2, a2[3][2]); FMA2(a2[3][3], v3, w3, a2[3][3]);
        }

        #pragma unroll
        for (int c = 0; c < 4; c++) {
            #pragma unroll
            for (int p = 0; p < 4; p++) {
                float lo, hi;
                UNPACK2(lo, hi, a2[p][c]);
                lo = fmaxf(lo, 0.0f);
                hi = fmaxf(hi, 0.0f);
                unsigned long long pk; PACK2(pk, lo, hi);
                *reinterpret_cast<unsigned long long*>(
                    &Ht[(j4 + c) * VP + nb + 2 * p]) = pk;
            }
        }
    }
    __syncthreads();

    // ---- GEMM2: Y[64][64] = H @ W2 + b2 ----
    {
        const int tx = t & 15;       // 16 * 4 = 64 d-columns
        const int ty = t >> 4;       // 16 groups * 4 nodes = 64 nodes
        const int d4 = tx * 4;
        const int nb = ty * 4;

        unsigned long long a2[2][4];   // [node-pair q][col c]
        {
            float4 bb = *reinterpret_cast<const float4*>(b2 + d4);
            unsigned long long d0, d1, d2, d3;
            PACK2(d0, bb.x, bb.x); PACK2(d1, bb.y, bb.y);
            PACK2(d2, bb.z, bb.z); PACK2(d3, bb.w, bb.w);
            a2[0][0] = d0; a2[0][1] = d1; a2[0][2] = d2; a2[0][3] = d3;
            a2[1][0] = d0; a2[1][1] = d1; a2[1][2] = d2; a2[1][3] = d3;
        }

        #pragma unroll 4
        for (int j = 0; j < H_FEAT; j++) {
            float4 w = *reinterpret_cast<const float4*>(W2 + j * D_FEAT + d4);
            unsigned long long w0, w1, w2, w3;
            PACK2(w0, w.x, w.x); PACK2(w1, w.y, w.y);
            PACK2(w2, w.z, w.z); PACK2(w3, w.w, w.w);
            const float* hrow = &Ht[j * VP + nb];
            unsigned long long h0 = *reinterpret_cast<const unsigned long long*>(hrow);
            unsigned long long h1 = *reinterpret_cast<const unsigned long long*>(hrow + 2);
            FMA2(a2[0][0], h0, w0, a2[0][0]); FMA2(a2[0][1], h0, w1, a2[0][1]);
            FMA2(a2[0][2], h0, w2, a2[0][2]); FMA2(a2[0][3], h0, w3, a2[0][3]);
            FMA2(a2[1][0], h1, w0, a2[1][0]); FMA2(a2[1][1], h1, w1, a2[1][1]);
            FMA2(a2[1][2], h1, w2, a2[1][2]); FMA2(a2[1][3], h1, w3, a2[1][3]);
        }

        #pragma unroll
        for (int q = 0; q < 2; q++) {
            float l0, h0, l1, h1, l2, h2, l3, h3;
            UNPACK2(l0, h0, a2[q][0]);
            UNPACK2(l1, h1, a2[q][1]);
            UNPACK2(l2, h2, a2[q][2]);
            UNPACK2(l3, h3, a2[q][3]);
            int node0 = n0 + nb + 2 * q;
            if (node0 < N)
                *reinterpret_cast<float4*>(out + (size_t)node0 * D_FEAT + d4) =
                    make_float4(l0, l1, l2, l3);
            if (node0 + 1 < N)
                *reinterpret_cast<float4*>(out + (size_t)(node0 + 1) * D_FEAT + d4) =
                    make_float4(h0, h1, h2, h3);
        }
    }
}

// ---------------------------------------------------------------------------
// Launch
// ---------------------------------------------------------------------------
extern "C" void kernel_launch(void* const* d_in, const int* in_sizes, int n_in,
                              void* d_out, int out_size) {
    const float* x   = (const float*)d_in[0];
    const float* W1  = (const float*)d_in[1];
    const float* b1  = (const float*)d_in[2];
    const float* W2  = (const float*)d_in[3];
    const float* b2  = (const float*)d_in[4];
    const float* eps = (const float*)d_in[5];
    const int*   ei  = (const int*)d_in[6];
    float* out = (float*)d_out;

    const int N = in_sizes[0] / D_FEAT;     // 50000
    const int E = in_sizes[6] / 2;          // 800000

    const int smem_bytes = (D_FEAT + H_FEAT) * VP * (int)sizeof(float); // 50688
    static int attr_set = 0;
    if (!attr_set) {
        cudaFuncSetAttribute(mlp_kernel,
                             cudaFuncAttributeMaxDynamicSharedMemorySize,
                             smem_bytes);
        attr_set = 1;
    }

    // 1) acc = (1+eps)*x
    int total4 = N * D_FEAT / 4;
    init_acc_kernel<<<(total4 + 255) / 256, 256>>>(x, eps, total4);

    // 2) edge scatter (8 lanes/edge, interleaved float4 chunks)
    long long threads = (long long)E * 8;
    int blocks = (int)((threads + 255) / 256);
    scatter_kernel<<<blocks, 256>>>(x, ei, E, N);

    // 3) fused MLP (64-node tiles)
    mlp_kernel<<<(N + NT - 1) / NT, 256, smem_bytes>>>(W1, b1, W2, b2, out, N);
}